// round 10
// baseline (speedup 1.0000x reference)
#include <cuda_runtime.h>
#include <cuda_bf16.h>
#include <math.h>
#include <stdint.h>

#define TOK   2048
#define HD    512
#define FD    2048
#define NE    8
#define NSLOTS (TOK*2)

// ================= device scratch =================
__device__ int   g_count[NE];
__device__ int   g_base[NE];
__device__ int   g_cursor[NE];
__device__ int   g_topi[TOK*2];
__device__ float g_topw[TOK*2];
__device__ int   g_perm[NSLOTS];
__device__ float g_wt[NSLOTS];
__device__ int   g_slot_of[TOK*2];
__device__ __align__(16) __nv_bfloat16 g_x_hi[(size_t)TOK*HD];
__device__ __align__(16) __nv_bfloat16 g_x_lo[(size_t)TOK*HD];
__device__ __align__(16) __nv_bfloat16 g_act_hi[(size_t)NSLOTS*FD];
__device__ __align__(16) __nv_bfloat16 g_act_lo[(size_t)NSLOTS*FD];
__device__ __align__(16) __nv_bfloat16 g_W1T_hi[(size_t)NE*FD*HD];  // [E][F][H]
__device__ __align__(16) __nv_bfloat16 g_W1T_lo[(size_t)NE*FD*HD];
__device__ __align__(16) __nv_bfloat16 g_W2T_hi[(size_t)NE*HD*FD];  // [E][H][F]
__device__ __align__(16) __nv_bfloat16 g_W2T_lo[(size_t)NE*HD*FD];
__device__ __align__(16) float g_y[(size_t)NSLOTS*HD];

// ================= PTX helpers (sm_80-portable only) =================
__device__ __forceinline__ uint32_t smem_u32(const void* p) {
    uint32_t a;
    asm("{ .reg .u64 t; cvta.to.shared.u64 t, %1; cvt.u32.u64 %0, t; }" : "=r"(a) : "l"(p));
    return a;
}
__device__ __forceinline__ void ldm4(uint32_t* r, uint32_t addr) {
    asm volatile("ldmatrix.sync.aligned.m8n8.x4.shared.b16 {%0,%1,%2,%3}, [%4];"
        : "=r"(r[0]), "=r"(r[1]), "=r"(r[2]), "=r"(r[3]) : "r"(addr));
}
__device__ __forceinline__ void mma_bf16(float* c, const uint32_t* a, const uint32_t* b) {
    asm volatile("mma.sync.aligned.m16n8k16.row.col.f32.bf16.bf16.f32 "
        "{%0,%1,%2,%3}, {%4,%5,%6,%7}, {%8,%9}, {%0,%1,%2,%3};"
        : "+f"(c[0]), "+f"(c[1]), "+f"(c[2]), "+f"(c[3])
        : "r"(a[0]), "r"(a[1]), "r"(a[2]), "r"(a[3]), "r"(b[0]), "r"(b[1]));
}
__device__ __forceinline__ void cpa16(uint32_t dst, const void* src) {
    asm volatile("cp.async.cg.shared.global [%0], [%1], 16;" :: "r"(dst), "l"(src));
}
#define CP_COMMIT() asm volatile("cp.async.commit_group;" ::: "memory")
template<int N> __device__ __forceinline__ void cp_wait() {
    asm volatile("cp.async.wait_group %0;" :: "n"(N) : "memory");
}

// split 8 fp32 -> bf16 hi (uint4) + bf16 lo (uint4)
__device__ __forceinline__ void split8(const float* f, uint4& hi, uint4& lo) {
    uint32_t h[8], l[8];
#pragma unroll
    for (int i = 0; i < 8; i++) {
        __nv_bfloat16 hb = __float2bfloat16(f[i]);
        float r = f[i] - __bfloat162float(hb);
        h[i] = (uint32_t)__bfloat16_as_ushort(hb);
        l[i] = (uint32_t)__bfloat16_as_ushort(__float2bfloat16(r));
    }
    hi.x = h[0] | (h[1] << 16); hi.y = h[2] | (h[3] << 16);
    hi.z = h[4] | (h[5] << 16); hi.w = h[6] | (h[7] << 16);
    lo.x = l[0] | (l[1] << 16); lo.y = l[2] | (l[3] << 16);
    lo.z = l[4] | (l[5] << 16); lo.w = l[6] | (l[7] << 16);
}

// ================= pre-pass: split x into bf16 planes =================
__global__ void split_x_kernel(const float* __restrict__ x) {
    int i8 = blockIdx.x * 256 + threadIdx.x;       // over TOK*HD/8
    const float* src = x + (size_t)i8 * 8;
    float f[8];
    float4 v0 = *(const float4*)(src);
    float4 v1 = *(const float4*)(src + 4);
    f[0]=v0.x; f[1]=v0.y; f[2]=v0.z; f[3]=v0.w;
    f[4]=v1.x; f[5]=v1.y; f[6]=v1.z; f[7]=v1.w;
    uint4 hi, lo;
    split8(f, hi, lo);
    *(uint4*)(g_x_hi + (size_t)i8 * 8) = hi;
    *(uint4*)(g_x_lo + (size_t)i8 * 8) = lo;
}

// ================= pre-pass: transpose + split weights =================
// W [e][K][N] fp32 -> plane_hi/lo [e][N][K] bf16.  Tile: 64 k x 32 n, block (32,8).
template<int K, int N, bool W1SEL>
__global__ void transpose_split(const float* __restrict__ W) {
    __shared__ float sm[32][65];                   // [n][k]
    __nv_bfloat16* Thi = W1SEL ? g_W1T_hi : g_W2T_hi;
    __nv_bfloat16* Tlo = W1SEL ? g_W1T_lo : g_W2T_lo;
    int e  = blockIdx.z;
    int n0 = blockIdx.x * 32, k0 = blockIdx.y * 64;
    int tx = threadIdx.x, ty = threadIdx.y;
    const float* Wp = W + (size_t)e * K * N;
#pragma unroll
    for (int j = 0; j < 8; j++) {
        int k = ty * 8 + j;
        sm[tx][k] = Wp[(size_t)(k0 + k) * N + n0 + tx];
    }
    __syncthreads();
    int t  = ty * 32 + tx;
    int n  = t >> 3;
    int ko = (t & 7) * 8;
    float f[8];
#pragma unroll
    for (int i = 0; i < 8; i++) f[i] = sm[n][ko + i];
    uint4 hi, lo;
    split8(f, hi, lo);
    size_t o = ((size_t)e * N + n0 + n) * K + k0 + ko;
    *(uint4*)(Thi + o) = hi;
    *(uint4*)(Tlo + o) = lo;
}

// ================= routing =================
__global__ void zero_kernel() {
    int i = threadIdx.x;
    if (i < NE) { g_count[i] = 0; g_cursor[i] = 0; }
}

__global__ void router_kernel(const float* __restrict__ x,
                              const float* __restrict__ Wg) {
    int warp = threadIdx.x >> 5, lane = threadIdx.x & 31;
    int t = blockIdx.x * 8 + warp;
    if (t >= TOK) return;
    float acc[NE];
#pragma unroll
    for (int e = 0; e < NE; e++) acc[e] = 0.f;
    const float4* xr = (const float4*)(x + (size_t)t * HD);
#pragma unroll
    for (int it = 0; it < HD/128; it++) {
        int i = it * 32 + lane;
        float4 xv = xr[i];
#pragma unroll
        for (int e = 0; e < NE; e++) {
            float4 w = ((const float4*)(Wg + e*HD))[i];
            acc[e] += xv.x*w.x + xv.y*w.y + xv.z*w.z + xv.w*w.w;
        }
    }
#pragma unroll
    for (int off = 16; off > 0; off >>= 1)
#pragma unroll
        for (int e = 0; e < NE; e++)
            acc[e] += __shfl_xor_sync(0xffffffffu, acc[e], off);
    if (lane == 0) {
        int i0 = 0;
#pragma unroll
        for (int e = 1; e < NE; e++) if (acc[e] > acc[i0]) i0 = e;
        int i1 = (i0 == 0) ? 1 : 0;
#pragma unroll
        for (int e = 0; e < NE; e++)
            if (e != i0 && acc[e] > acc[i1]) i1 = e;
        float e1 = expf(acc[i1] - acc[i0]);
        float inv = 1.f / (1.f + e1);
        g_topi[t*2+0] = i0; g_topw[t*2+0] = inv;
        g_topi[t*2+1] = i1; g_topw[t*2+1] = e1 * inv;
        atomicAdd(&g_count[i0], 1);
        atomicAdd(&g_count[i1], 1);
    }
}

__global__ void scan_kernel() {
    int s = 0;
#pragma unroll
    for (int e = 0; e < NE; e++) { g_base[e] = s; s += g_count[e]; }
}

__global__ void scatter_kernel() {
    int t = blockIdx.x * 256 + threadIdx.x;
    if (t >= TOK) return;
#pragma unroll
    for (int k = 0; k < 2; k++) {
        int e = g_topi[t*2+k];
        int pos = atomicAdd(&g_cursor[e], 1);
        int slot = g_base[e] + pos;
        g_perm[slot] = t;
        g_wt[slot]   = g_topw[t*2+k];
        g_slot_of[t*2+k] = slot;
    }
}

// ================= grouped GEMM: cp.async 3-stage pipeline + mma.sync =================
// CTA 128x128, K-chunk 16. STATIC smem: 3 stages x 4 planes x (128 rows x 32B) = 48KB.
// Row swizzle: physical 16B chunk = c ^ ((row>>2)&1)  -> conflict-free ldmatrix + STS.
// bf16x3: hi*hi + hi*lo + lo*hi.
// PASS1: C = silu(gather(x planes) @ W1T + b1) -> g_act planes
// PASS2: C = (act planes @ W2T + b2) * wt      -> g_y fp32
#define PLB   4096            // bytes per plane (128 rows x 32B)
#define STGB  (4*PLB)         // bytes per stage

template<int KDIM, int NDIM, bool PASS1>
__global__ __launch_bounds__(256, 2)
void moe_gemm(const float* __restrict__ bias) {
    __shared__ __align__(16) char smem[3*STGB];   // 49152 B static

    int e   = blockIdx.z;
    int cnt = g_count[e];
    int m0  = blockIdx.y * 128;
    if (m0 >= cnt) return;
    int n0   = blockIdx.x * 128;
    int base = g_base[e];

    int tid = threadIdx.x, wid = tid >> 5, lane = tid & 31;
    int wm = wid & 3, wn = wid >> 2;
    uint32_t smb = smem_u32(smem);

    const __nv_bfloat16* Ahi_g = PASS1 ? g_x_hi : g_act_hi;
    const __nv_bfloat16* Alo_g = PASS1 ? g_x_lo : g_act_lo;
    const __nv_bfloat16* Bhi_g = PASS1 ? g_W1T_hi : g_W2T_hi;
    const __nv_bfloat16* Blo_g = PASS1 ? g_W1T_lo : g_W2T_lo;

    // ---- loader mapping: plane p = tid>>6, rows 2t and 2t+1 (t = tid&63) ----
    int p  = tid >> 6, t = tid & 63;
    int r0 = 2*t, r1 = 2*t + 1;
    const char *src0, *src1;
    if (p < 2) {
        int mr0 = m0 + r0; if (mr0 >= cnt) mr0 = cnt - 1;
        int mr1 = m0 + r1; if (mr1 >= cnt) mr1 = cnt - 1;
        int ar0 = PASS1 ? g_perm[base + mr0] : (base + mr0);
        int ar1 = PASS1 ? g_perm[base + mr1] : (base + mr1);
        const __nv_bfloat16* pl = (p == 0) ? Ahi_g : Alo_g;
        src0 = (const char*)(pl + (size_t)ar0 * KDIM);
        src1 = (const char*)(pl + (size_t)ar1 * KDIM);
    } else {
        const __nv_bfloat16* pl = (p == 2) ? Bhi_g : Blo_g;
        src0 = (const char*)(pl + ((size_t)e * NDIM + n0 + r0) * KDIM);
        src1 = (const char*)(pl + ((size_t)e * NDIM + n0 + r1) * KDIM);
    }
    int s0 = (r0 >> 2) & 1, s1 = (r1 >> 2) & 1;
    uint32_t d00 = (uint32_t)(p*PLB + r0*32 + s0*16);        // logical chunk0
    uint32_t d01 = (uint32_t)(p*PLB + r0*32 + (s0^1)*16);    // logical chunk1
    uint32_t d10 = (uint32_t)(p*PLB + r1*32 + s1*16);
    uint32_t d11 = (uint32_t)(p*PLB + r1*32 + (s1^1)*16);

    float acc[2][8][4];
#pragma unroll
    for (int a = 0; a < 2; a++)
#pragma unroll
        for (int b = 0; b < 8; b++)
#pragma unroll
            for (int c = 0; c < 4; c++) acc[a][b][c] = 0.f;

    // ldmatrix lane addressing (R3-proven fragment mapping + swizzle)
    int a_r = lane & 15, ac = lane >> 4;          // A: row within 16, k-chunk 0/1
    int b_n = ((lane >> 4) & 1) * 8 + (lane & 7); // B: n-row within 16
    int bc  = (lane >> 3) & 1;                    // B: k-chunk 0/1

    const int NCH = KDIM / 16;

    // prologue: stages 0,1 = chunks 0,1
#pragma unroll
    for (int ci = 0; ci < 2; ci++) {
        uint32_t sg = smb + ci * STGB;
        uint32_t go = (uint32_t)ci * 32;
        cpa16(sg + d00, src0 + go);  cpa16(sg + d01, src0 + go + 16);
        cpa16(sg + d10, src1 + go);  cpa16(sg + d11, src1 + go + 16);
        CP_COMMIT();
    }

    for (int ci = 0; ci < NCH; ci++) {
        if (ci < NCH - 1) cp_wait<1>(); else cp_wait<0>();
        __syncthreads();
        if (ci + 2 < NCH) {
            uint32_t sg = smb + ((ci + 2) % 3) * STGB;
            uint32_t go = (uint32_t)(ci + 2) * 32;
            cpa16(sg + d00, src0 + go);  cpa16(sg + d01, src0 + go + 16);
            cpa16(sg + d10, src1 + go);  cpa16(sg + d11, src1 + go + 16);
            CP_COMMIT();
        }

        uint32_t sb = smb + (ci % 3) * STGB;
        uint32_t ah[2][4], al[2][4];
#pragma unroll
        for (int mt = 0; mt < 2; mt++) {
            int row = wm*32 + mt*16 + a_r;
            uint32_t co = (uint32_t)((ac ^ ((row >> 2) & 1)) * 16);
            ldm4(ah[mt], sb + row*32 + co);
            ldm4(al[mt], sb + PLB + row*32 + co);
        }
#pragma unroll
        for (int p4 = 0; p4 < 4; p4++) {
            int row = wn*64 + p4*16 + b_n;
            uint32_t co = (uint32_t)((bc ^ ((row >> 2) & 1)) * 16);
            uint32_t bh[4], bl[4];
            ldm4(bh, sb + 2*PLB + row*32 + co);
            ldm4(bl, sb + 3*PLB + row*32 + co);
#pragma unroll
            for (int mt = 0; mt < 2; mt++) {
#pragma unroll
                for (int q = 0; q < 2; q++) {
                    float* c = acc[mt][p4*2 + q];
                    mma_bf16(c, ah[mt], &bh[q*2]);
                    mma_bf16(c, ah[mt], &bl[q*2]);
                    mma_bf16(c, al[mt], &bh[q*2]);
                }
            }
        }
    }

    // ---- epilogue ----
    int rbase = wm*32 + (lane >> 2);
    int cbase = n0 + wn*64 + (lane & 3)*2;
#pragma unroll
    for (int mt = 0; mt < 2; mt++) {
#pragma unroll
        for (int sub = 0; sub < 2; sub++) {
            int m = m0 + rbase + mt*16 + sub*8;
            if (m >= cnt) continue;
            int slot = base + m;
            float wtv = PASS1 ? 1.f : g_wt[slot];
#pragma unroll
            for (int nt = 0; nt < 8; nt++) {
                int n = cbase + nt*8;
                float v0 = acc[mt][nt][sub*2+0] + __ldg(&bias[e*NDIM + n]);
                float v1 = acc[mt][nt][sub*2+1] + __ldg(&bias[e*NDIM + n + 1]);
                if (PASS1) {
                    v0 = v0 / (1.f + __expf(-v0));
                    v1 = v1 / (1.f + __expf(-v1));
                    __nv_bfloat16 h0 = __float2bfloat16(v0);
                    __nv_bfloat16 h1 = __float2bfloat16(v1);
                    __nv_bfloat16 l0 = __float2bfloat16(v0 - __bfloat162float(h0));
                    __nv_bfloat16 l1 = __float2bfloat16(v1 - __bfloat162float(h1));
                    uint32_t ph = (uint32_t)__bfloat16_as_ushort(h0) | ((uint32_t)__bfloat16_as_ushort(h1) << 16);
                    uint32_t pl = (uint32_t)__bfloat16_as_ushort(l0) | ((uint32_t)__bfloat16_as_ushort(l1) << 16);
                    *(uint32_t*)(g_act_hi + (size_t)slot * NDIM + n) = ph;
                    *(uint32_t*)(g_act_lo + (size_t)slot * NDIM + n) = pl;
                } else {
                    float2 o; o.x = v0 * wtv; o.y = v1 * wtv;
                    *(float2*)(g_y + (size_t)slot * NDIM + n) = o;
                }
            }
        }
    }
}

// ================= combine =================
__global__ void combine_kernel(float* __restrict__ out) {
    int idx = blockIdx.x * 256 + threadIdx.x;
    if (idx >= TOK * (HD/4)) return;
    int t  = idx / (HD/4);
    int h4 = idx % (HD/4);
    int s0 = g_slot_of[t*2+0];
    int s1 = g_slot_of[t*2+1];
    float4 a = *(const float4*)&g_y[(size_t)s0 * HD + h4*4];
    float4 b = *(const float4*)&g_y[(size_t)s1 * HD + h4*4];
    float4 o;
    o.x = a.x + b.x; o.y = a.y + b.y; o.z = a.z + b.z; o.w = a.w + b.w;
    *(float4*)&out[(size_t)t * HD + h4*4] = o;
}

// ================= launch =================
extern "C" void kernel_launch(void* const* d_in, const int* in_sizes, int n_in,
                              void* d_out, int out_size) {
    const float* x  = (const float*)d_in[0];
    const float* Wg = (const float*)d_in[1];
    const float* W1 = (const float*)d_in[2];  // [8][512][2048]
    const float* b1 = (const float*)d_in[3];
    const float* W2 = (const float*)d_in[4];  // [8][2048][512]
    const float* b2 = (const float*)d_in[5];
    float* out = (float*)d_out;

    zero_kernel<<<1, 32>>>();
    split_x_kernel<<<TOK*HD/8/256, 256>>>(x);
    transpose_split<HD, FD, true ><<<dim3(FD/32, HD/64, NE), dim3(32, 8)>>>(W1);
    transpose_split<FD, HD, false><<<dim3(HD/32, FD/64, NE), dim3(32, 8)>>>(W2);
    router_kernel<<<TOK/8, 256>>>(x, Wg);
    scan_kernel<<<1, 1>>>();
    scatter_kernel<<<TOK/256, 256>>>();

    // Pass A: gather(x planes) @ W1T -> silu -> g_act planes
    moe_gemm<HD, FD, true><<<dim3(FD/128, 32, NE), 256>>>(b1);
    // Pass B: act planes @ W2T -> *wt -> g_y
    moe_gemm<FD, HD, false><<<dim3(HD/128, 32, NE), 256>>>(b2);

    combine_kernel<<<(TOK*(HD/4) + 255)/256, 256>>>(out);
}

// round 11
// speedup vs baseline: 1.8391x; 1.8391x over previous
#include <cuda_runtime.h>
#include <cuda_fp16.h>
#include <math.h>
#include <stdint.h>

#define TOK   2048
#define HD    512
#define FD    2048
#define NE    8
#define NSLOTS (TOK*2)

// ================= device scratch =================
__device__ int   g_count[NE];
__device__ int   g_base[NE];
__device__ int   g_cursor[NE];
__device__ int   g_topi[TOK*2];
__device__ float g_topw[TOK*2];
__device__ int   g_perm[NSLOTS];
__device__ float g_wt[NSLOTS];
__device__ int   g_slot_of[TOK*2];
__device__ __align__(16) __half g_xh [(size_t)TOK*HD];      // fp16(x)
__device__ __align__(16) __half g_acth[(size_t)NSLOTS*FD];  // fp16(silu(h))
__device__ __align__(16) __half g_w1t[(size_t)NE*FD*HD];    // [E][F][H] fp16(W1^T)
__device__ __align__(16) __half g_w2t[(size_t)NE*HD*FD];    // [E][H][F] fp16(W2^T)
__device__ __align__(16) float  g_y[(size_t)NSLOTS*HD];

// ================= PTX helpers (sm_80-portable only) =================
__device__ __forceinline__ uint32_t smem_u32(const void* p) {
    uint32_t a;
    asm("{ .reg .u64 t; cvta.to.shared.u64 t, %1; cvt.u32.u64 %0, t; }" : "=r"(a) : "l"(p));
    return a;
}
__device__ __forceinline__ void ldm4(uint32_t* r, uint32_t addr) {
    asm volatile("ldmatrix.sync.aligned.m8n8.x4.shared.b16 {%0,%1,%2,%3}, [%4];"
        : "=r"(r[0]), "=r"(r[1]), "=r"(r[2]), "=r"(r[3]) : "r"(addr));
}
__device__ __forceinline__ void mma_fp16(float* c, const uint32_t* a, const uint32_t* b) {
    asm volatile("mma.sync.aligned.m16n8k16.row.col.f32.f16.f16.f32 "
        "{%0,%1,%2,%3}, {%4,%5,%6,%7}, {%8,%9}, {%0,%1,%2,%3};"
        : "+f"(c[0]), "+f"(c[1]), "+f"(c[2]), "+f"(c[3])
        : "r"(a[0]), "r"(a[1]), "r"(a[2]), "r"(a[3]), "r"(b[0]), "r"(b[1]));
}
__device__ __forceinline__ void cpa16(uint32_t dst, const void* src) {
    asm volatile("cp.async.cg.shared.global [%0], [%1], 16;" :: "r"(dst), "l"(src));
}
#define CP_COMMIT() asm volatile("cp.async.commit_group;" ::: "memory")
template<int N> __device__ __forceinline__ void cp_wait() {
    asm volatile("cp.async.wait_group %0;" :: "n"(N) : "memory");
}

// pack 8 fp32 -> 8 fp16 in a uint4
__device__ __forceinline__ void pack8h(const float* f, uint4& o) {
    uint32_t h[8];
#pragma unroll
    for (int i = 0; i < 8; i++)
        h[i] = (uint32_t)__half_as_ushort(__float2half_rn(f[i]));
    o.x = h[0] | (h[1] << 16); o.y = h[2] | (h[3] << 16);
    o.z = h[4] | (h[5] << 16); o.w = h[6] | (h[7] << 16);
}

// ================= pre-pass: convert x to fp16 =================
__global__ void cvt_x_kernel(const float* __restrict__ x) {
    int i8 = blockIdx.x * 256 + threadIdx.x;       // over TOK*HD/8
    const float* src = x + (size_t)i8 * 8;
    float f[8];
    float4 v0 = *(const float4*)(src);
    float4 v1 = *(const float4*)(src + 4);
    f[0]=v0.x; f[1]=v0.y; f[2]=v0.z; f[3]=v0.w;
    f[4]=v1.x; f[5]=v1.y; f[6]=v1.z; f[7]=v1.w;
    uint4 o; pack8h(f, o);
    *(uint4*)(g_xh + (size_t)i8 * 8) = o;
}

// ================= pre-pass: transpose + convert weights =================
// W [e][K][N] fp32 -> plane [e][N][K] fp16.  Tile: 64 k x 32 n, block (32,8).
template<int K, int N, bool W1SEL>
__global__ void transpose_cvt(const float* __restrict__ W) {
    __shared__ float sm[32][65];                   // [n][k]
    __half* T = W1SEL ? g_w1t : g_w2t;
    int e  = blockIdx.z;
    int n0 = blockIdx.x * 32, k0 = blockIdx.y * 64;
    int tx = threadIdx.x, ty = threadIdx.y;
    const float* Wp = W + (size_t)e * K * N;
#pragma unroll
    for (int j = 0; j < 8; j++) {
        int k = ty * 8 + j;
        sm[tx][k] = Wp[(size_t)(k0 + k) * N + n0 + tx];
    }
    __syncthreads();
    int t  = ty * 32 + tx;
    int n  = t >> 3;
    int ko = (t & 7) * 8;
    float f[8];
#pragma unroll
    for (int i = 0; i < 8; i++) f[i] = sm[n][ko + i];
    uint4 o; pack8h(f, o);
    *(uint4*)(T + ((size_t)e * N + n0 + n) * K + k0 + ko) = o;
}

// ================= routing =================
__global__ void zero_kernel() {
    int i = threadIdx.x;
    if (i < NE) { g_count[i] = 0; g_cursor[i] = 0; }
}

__global__ void router_kernel(const float* __restrict__ x,
                              const float* __restrict__ Wg) {
    int warp = threadIdx.x >> 5, lane = threadIdx.x & 31;
    int t = blockIdx.x * 8 + warp;
    if (t >= TOK) return;
    float acc[NE];
#pragma unroll
    for (int e = 0; e < NE; e++) acc[e] = 0.f;
    const float4* xr = (const float4*)(x + (size_t)t * HD);
#pragma unroll
    for (int it = 0; it < HD/128; it++) {
        int i = it * 32 + lane;
        float4 xv = xr[i];
#pragma unroll
        for (int e = 0; e < NE; e++) {
            float4 w = ((const float4*)(Wg + e*HD))[i];
            acc[e] += xv.x*w.x + xv.y*w.y + xv.z*w.z + xv.w*w.w;
        }
    }
#pragma unroll
    for (int off = 16; off > 0; off >>= 1)
#pragma unroll
        for (int e = 0; e < NE; e++)
            acc[e] += __shfl_xor_sync(0xffffffffu, acc[e], off);
    if (lane == 0) {
        int i0 = 0;
#pragma unroll
        for (int e = 1; e < NE; e++) if (acc[e] > acc[i0]) i0 = e;
        int i1 = (i0 == 0) ? 1 : 0;
#pragma unroll
        for (int e = 0; e < NE; e++)
            if (e != i0 && acc[e] > acc[i1]) i1 = e;
        float e1 = expf(acc[i1] - acc[i0]);
        float inv = 1.f / (1.f + e1);
        g_topi[t*2+0] = i0; g_topw[t*2+0] = inv;
        g_topi[t*2+1] = i1; g_topw[t*2+1] = e1 * inv;
        atomicAdd(&g_count[i0], 1);
        atomicAdd(&g_count[i1], 1);
    }
}

__global__ void scan_kernel() {
    int s = 0;
#pragma unroll
    for (int e = 0; e < NE; e++) { g_base[e] = s; s += g_count[e]; }
}

__global__ void scatter_kernel() {
    int t = blockIdx.x * 256 + threadIdx.x;
    if (t >= TOK) return;
#pragma unroll
    for (int k = 0; k < 2; k++) {
        int e = g_topi[t*2+k];
        int pos = atomicAdd(&g_cursor[e], 1);
        int slot = g_base[e] + pos;
        g_perm[slot] = t;
        g_wt[slot]   = g_topw[t*2+k];
        g_slot_of[t*2+k] = slot;
    }
}

// ================= grouped GEMM: fp16 mma.sync, cp.async 3-stage =================
// CTA 128x128, K-chunk 16. STATIC smem: 3 stages x 2 planes x (128 rows x 32B) = 24KB.
// Row swizzle: physical 16B chunk = c ^ ((row>>2)&1)  (R10-proven conflict-free).
// PASS1: C = silu(gather(fp16 x) @ W1T + b1) -> g_acth fp16
// PASS2: C = (fp16 act @ W2T + b2) * wt      -> g_y fp32
#define PLB   4096            // bytes per plane (128 rows x 32B)
#define STGB  (2*PLB)         // bytes per stage (A plane + B plane)

template<int KDIM, int NDIM, bool PASS1>
__global__ __launch_bounds__(256, 2)
void moe_gemm(const float* __restrict__ bias) {
    __shared__ __align__(16) char smem[3*STGB];   // 24576 B static

    int e   = blockIdx.z;
    int cnt = g_count[e];
    int m0  = blockIdx.y * 128;
    if (m0 >= cnt) return;
    int n0   = blockIdx.x * 128;
    int base = g_base[e];

    int tid = threadIdx.x, wid = tid >> 5, lane = tid & 31;
    int wm = wid & 3, wn = wid >> 2;
    uint32_t smb = smem_u32(smem);

    const __half* A_g = PASS1 ? g_xh : g_acth;
    const __half* B_g = PASS1 ? g_w1t : g_w2t;

    // ---- loader mapping: plane p = tid>>7 (0=A,1=B), row r = tid&127 ----
    int p = tid >> 7, r = tid & 127;
    const char* src;
    if (p == 0) {
        int mr = m0 + r; if (mr >= cnt) mr = cnt - 1;
        int ar = PASS1 ? g_perm[base + mr] : (base + mr);
        src = (const char*)(A_g + (size_t)ar * KDIM);
    } else {
        src = (const char*)(B_g + ((size_t)e * NDIM + n0 + r) * KDIM);
    }
    int s = (r >> 2) & 1;
    uint32_t d0 = (uint32_t)(p*PLB + r*32 + s*16);        // physical slot of logical chunk0
    uint32_t d1 = (uint32_t)(p*PLB + r*32 + (s^1)*16);    // physical slot of logical chunk1

    float acc[2][8][4];
#pragma unroll
    for (int a = 0; a < 2; a++)
#pragma unroll
        for (int b = 0; b < 8; b++)
#pragma unroll
            for (int c = 0; c < 4; c++) acc[a][b][c] = 0.f;

    // ldmatrix lane addressing (R3-proven fragment mapping + swizzle)
    int a_r = lane & 15, ac = lane >> 4;          // A: row within 16, k-chunk 0/1
    int b_n = ((lane >> 4) & 1) * 8 + (lane & 7); // B: n-row within 16
    int bc  = (lane >> 3) & 1;                    // B: k-chunk 0/1

    const int NCH = KDIM / 16;

    // prologue: stages 0,1 = chunks 0,1
#pragma unroll
    for (int ci = 0; ci < 2; ci++) {
        uint32_t sg = smb + ci * STGB;
        uint32_t go = (uint32_t)ci * 32;
        cpa16(sg + d0, src + go);
        cpa16(sg + d1, src + go + 16);
        CP_COMMIT();
    }

    for (int ci = 0; ci < NCH; ci++) {
        if (ci < NCH - 1) cp_wait<1>(); else cp_wait<0>();
        __syncthreads();
        if (ci + 2 < NCH) {
            uint32_t sg = smb + ((ci + 2) % 3) * STGB;
            uint32_t go = (uint32_t)(ci + 2) * 32;
            cpa16(sg + d0, src + go);
            cpa16(sg + d1, src + go + 16);
            CP_COMMIT();
        }

        uint32_t sb = smb + (ci % 3) * STGB;
        uint32_t ah[2][4];
#pragma unroll
        for (int mt = 0; mt < 2; mt++) {
            int row = wm*32 + mt*16 + a_r;
            uint32_t co = (uint32_t)((ac ^ ((row >> 2) & 1)) * 16);
            ldm4(ah[mt], sb + row*32 + co);
        }
#pragma unroll
        for (int p4 = 0; p4 < 4; p4++) {
            int row = wn*64 + p4*16 + b_n;
            uint32_t co = (uint32_t)((bc ^ ((row >> 2) & 1)) * 16);
            uint32_t bh[4];
            ldm4(bh, sb + PLB + row*32 + co);
#pragma unroll
            for (int mt = 0; mt < 2; mt++) {
#pragma unroll
                for (int q = 0; q < 2; q++)
                    mma_fp16(acc[mt][p4*2 + q], ah[mt], &bh[q*2]);
            }
        }
    }

    // ---- epilogue ----
    int rbase = wm*32 + (lane >> 2);
    int cbase = n0 + wn*64 + (lane & 3)*2;
#pragma unroll
    for (int mt = 0; mt < 2; mt++) {
#pragma unroll
        for (int sub = 0; sub < 2; sub++) {
            int m = m0 + rbase + mt*16 + sub*8;
            if (m >= cnt) continue;
            int slot = base + m;
            float wtv = PASS1 ? 1.f : g_wt[slot];
#pragma unroll
            for (int nt = 0; nt < 8; nt++) {
                int n = cbase + nt*8;
                float v0 = acc[mt][nt][sub*2+0] + __ldg(&bias[e*NDIM + n]);
                float v1 = acc[mt][nt][sub*2+1] + __ldg(&bias[e*NDIM + n + 1]);
                if (PASS1) {
                    v0 = v0 / (1.f + __expf(-v0));
                    v1 = v1 / (1.f + __expf(-v1));
                    uint32_t pk = (uint32_t)__half_as_ushort(__float2half_rn(v0))
                                | ((uint32_t)__half_as_ushort(__float2half_rn(v1)) << 16);
                    *(uint32_t*)(g_acth + (size_t)slot * NDIM + n) = pk;
                } else {
                    float2 o; o.x = v0 * wtv; o.y = v1 * wtv;
                    *(float2*)(g_y + (size_t)slot * NDIM + n) = o;
                }
            }
        }
    }
}

// ================= combine =================
__global__ void combine_kernel(float* __restrict__ out) {
    int idx = blockIdx.x * 256 + threadIdx.x;
    if (idx >= TOK * (HD/4)) return;
    int t  = idx / (HD/4);
    int h4 = idx % (HD/4);
    int s0 = g_slot_of[t*2+0];
    int s1 = g_slot_of[t*2+1];
    float4 a = *(const float4*)&g_y[(size_t)s0 * HD + h4*4];
    float4 b = *(const float4*)&g_y[(size_t)s1 * HD + h4*4];
    float4 o;
    o.x = a.x + b.x; o.y = a.y + b.y; o.z = a.z + b.z; o.w = a.w + b.w;
    *(float4*)&out[(size_t)t * HD + h4*4] = o;
}

// ================= launch =================
extern "C" void kernel_launch(void* const* d_in, const int* in_sizes, int n_in,
                              void* d_out, int out_size) {
    const float* x  = (const float*)d_in[0];
    const float* Wg = (const float*)d_in[1];
    const float* W1 = (const float*)d_in[2];  // [8][512][2048]
    const float* b1 = (const float*)d_in[3];
    const float* W2 = (const float*)d_in[4];  // [8][2048][512]
    const float* b2 = (const float*)d_in[5];
    float* out = (float*)d_out;

    zero_kernel<<<1, 32>>>();
    cvt_x_kernel<<<TOK*HD/8/256, 256>>>(x);
    transpose_cvt<HD, FD, true ><<<dim3(FD/32, HD/64, NE), dim3(32, 8)>>>(W1);
    transpose_cvt<FD, HD, false><<<dim3(HD/32, FD/64, NE), dim3(32, 8)>>>(W2);
    router_kernel<<<TOK/8, 256>>>(x, Wg);
    scan_kernel<<<1, 1>>>();
    scatter_kernel<<<TOK/256, 256>>>();

    // Pass A: gather(fp16 x) @ W1T -> silu -> g_acth
    moe_gemm<HD, FD, true><<<dim3(FD/128, 32, NE), 256>>>(b1);
    // Pass B: g_acth @ W2T -> *wt -> g_y
    moe_gemm<FD, HD, false><<<dim3(HD/128, 32, NE), 256>>>(b2);

    combine_kernel<<<(TOK*(HD/4) + 255)/256, 256>>>(out);
}

// round 15
// speedup vs baseline: 1.8425x; 1.0018x over previous
#include <cuda_runtime.h>
#include <cuda_fp16.h>
#include <math.h>
#include <stdint.h>

#define TOK   2048
#define HD    512
#define FD    2048
#define NE    8
#define NSLOTS (TOK*2)

// ---------------- device scratch ----------------
__device__ int   g_count[NE];
__device__ int   g_base[NE];
__device__ int   g_cursor[NE];
__device__ int   g_topi[TOK*2];
__device__ float g_topw[TOK*2];
__device__ int   g_perm[NSLOTS];
__device__ float g_wt[NSLOTS];
__device__ int   g_slot_of[TOK*2];
__device__ __align__(16) __half gx16  [(size_t)TOK*HD];     // fp16(x)
__device__ __align__(16) __half gact16[(size_t)NSLOTS*FD];  // fp16(silu(h))
__device__ __align__(16) __half gw1   [(size_t)NE*FD*HD];   // [E][F][H] fp16(W1^T)
__device__ __align__(16) __half gw2   [(size_t)NE*HD*FD];   // [E][H][F] fp16(W2^T)
__device__ __align__(16) float  gyy   [(size_t)NSLOTS*HD];

// ---------------- PTX helpers (sm_80-portable only) ----------------
__device__ __forceinline__ uint32_t smaddr(const void* p) {
    uint32_t a;
    asm("{ .reg .u64 t; cvta.to.shared.u64 t, %1; cvt.u32.u64 %0, t; }" : "=r"(a) : "l"(p));
    return a;
}
__device__ __forceinline__ void ldmx4(uint32_t* r, uint32_t addr) {
    asm volatile("ldmatrix.sync.aligned.m8n8.x4.shared.b16 {%0,%1,%2,%3}, [%4];"
        : "=r"(r[0]), "=r"(r[1]), "=r"(r[2]), "=r"(r[3]) : "r"(addr));
}
__device__ __forceinline__ void hmma(float* c, const uint32_t* a, const uint32_t* b) {
    asm volatile("mma.sync.aligned.m16n8k16.row.col.f32.f16.f16.f32 "
        "{%0,%1,%2,%3}, {%4,%5,%6,%7}, {%8,%9}, {%0,%1,%2,%3};"
        : "+f"(c[0]), "+f"(c[1]), "+f"(c[2]), "+f"(c[3])
        : "r"(a[0]), "r"(a[1]), "r"(a[2]), "r"(a[3]), "r"(b[0]), "r"(b[1]));
}
__device__ __forceinline__ void cp16(uint32_t dst, const void* src) {
    asm volatile("cp.async.cg.shared.global [%0], [%1], 16;" :: "r"(dst), "l"(src));
}
#define CPC() asm volatile("cp.async.commit_group;" ::: "memory")
template<int N> __device__ __forceinline__ void cpw() {
    asm volatile("cp.async.wait_group %0;" :: "n"(N) : "memory");
}

// pack 8 fp32 -> 8 fp16 (uint4)
__device__ __forceinline__ void h8pack(const float* f, uint4& o) {
    uint32_t h[8];
#pragma unroll
    for (int i = 0; i < 8; i++)
        h[i] = (uint32_t)__half_as_ushort(__float2half_rn(f[i]));
    o.x = h[0] | (h[1] << 16); o.y = h[2] | (h[3] << 16);
    o.z = h[4] | (h[5] << 16); o.w = h[6] | (h[7] << 16);
}

// ---------------- pre-pass: W [e][K][N] fp32 -> [e][N][K] fp16 ----------------
template<int K, int N, bool W1SEL>
__global__ void w_transpose_kernel(const float* __restrict__ W) {
    __shared__ float sm[32][65];                   // [n][k]
    __half* T = W1SEL ? gw1 : gw2;
    int e  = blockIdx.z;
    int n0 = blockIdx.x * 32, k0 = blockIdx.y * 64;
    int tx = threadIdx.x, ty = threadIdx.y;
    const float* Wp = W + (size_t)e * K * N;
#pragma unroll
    for (int j = 0; j < 8; j++)
        sm[tx][ty * 8 + j] = Wp[(size_t)(k0 + ty * 8 + j) * N + n0 + tx];
    __syncthreads();
    int t  = ty * 32 + tx;
    int n  = t >> 3;
    int ko = (t & 7) * 8;
    float f[8];
#pragma unroll
    for (int i = 0; i < 8; i++) f[i] = sm[n][ko + i];
    uint4 o; h8pack(f, o);
    *(uint4*)(T + ((size_t)e * N + n0 + n) * K + k0 + ko) = o;
}

// ---------------- routing (fused: also emits fp16 x) ----------------
__global__ void init_kernel() {
    int i = threadIdx.x;
    if (i < NE) { g_count[i] = 0; g_cursor[i] = 0; }
}

__global__ void router_cvt_kernel(const float* __restrict__ x,
                                  const float* __restrict__ Wg) {
    int warp = threadIdx.x >> 5, lane = threadIdx.x & 31;
    int t = blockIdx.x * 8 + warp;
    if (t >= TOK) return;
    float acc[NE];
#pragma unroll
    for (int e = 0; e < NE; e++) acc[e] = 0.f;
    const float4* xr = (const float4*)(x + (size_t)t * HD);
#pragma unroll
    for (int it = 0; it < HD/128; it++) {
        int i = it * 32 + lane;
        float4 xv = xr[i];
        // fused fp16 conversion of x
        uint2 pk;
        pk.x = (uint32_t)__half_as_ushort(__float2half_rn(xv.x))
             | ((uint32_t)__half_as_ushort(__float2half_rn(xv.y)) << 16);
        pk.y = (uint32_t)__half_as_ushort(__float2half_rn(xv.z))
             | ((uint32_t)__half_as_ushort(__float2half_rn(xv.w)) << 16);
        *(uint2*)(gx16 + (size_t)t * HD + i * 4) = pk;
#pragma unroll
        for (int e = 0; e < NE; e++) {
            float4 w = ((const float4*)(Wg + e*HD))[i];
            acc[e] += xv.x*w.x + xv.y*w.y + xv.z*w.z + xv.w*w.w;
        }
    }
#pragma unroll
    for (int off = 16; off > 0; off >>= 1)
#pragma unroll
        for (int e = 0; e < NE; e++)
            acc[e] += __shfl_xor_sync(0xffffffffu, acc[e], off);
    if (lane == 0) {
        int i0 = 0;
#pragma unroll
        for (int e = 1; e < NE; e++) if (acc[e] > acc[i0]) i0 = e;
        int i1 = (i0 == 0) ? 1 : 0;
#pragma unroll
        for (int e = 0; e < NE; e++)
            if (e != i0 && acc[e] > acc[i1]) i1 = e;
        float e1 = expf(acc[i1] - acc[i0]);
        float inv = 1.f / (1.f + e1);
        g_topi[t*2+0] = i0; g_topw[t*2+0] = inv;
        g_topi[t*2+1] = i1; g_topw[t*2+1] = e1 * inv;
        atomicAdd(&g_count[i0], 1);
        atomicAdd(&g_count[i1], 1);
    }
}

__global__ void scan_kernel() {
    int s = 0;
#pragma unroll
    for (int e = 0; e < NE; e++) { g_base[e] = s; s += g_count[e]; }
}

__global__ void scatter_kernel() {
    int t = blockIdx.x * 256 + threadIdx.x;
    if (t >= TOK) return;
#pragma unroll
    for (int k = 0; k < 2; k++) {
        int e = g_topi[t*2+k];
        int pos = atomicAdd(&g_cursor[e], 1);
        int slot = g_base[e] + pos;
        g_perm[slot] = t;
        g_wt[slot]   = g_topw[t*2+k];
        g_slot_of[t*2+k] = slot;
    }
}

// ---------------- grouped GEMM: fp16 mma.sync, paired K16 chunks, 4 stages ----------------
// Layout per stage (8KB = A plane 4KB + B plane 4KB), 32B rows, swizzle
// physical 16B half = h ^ ((row>>2)&1)  — all byte-identical to the R11 build.
// New: chunks processed in PAIRS: one wait+barrier per 2 chunks. Stage of chunk
// ci = ci & 3; iteration computes (ci, ci+1) and issues (ci+2, ci+3) into the
// two stages freed in the previous iteration (barrier guarantees safety).
#define PLB   4096            // bytes per plane (128 rows x 32B)
#define STGB  (2*PLB)         // bytes per stage

template<int KDIM, int NDIM, bool PASS1>
__global__ __launch_bounds__(256, 2)
void moe_gemm_p2(const float* __restrict__ bias) {
    __shared__ __align__(16) char smem[4*STGB];   // 32768 B static

    int e   = blockIdx.z;
    int cnt = g_count[e];
    int m0  = blockIdx.y * 128;
    if (m0 >= cnt) return;
    int n0   = blockIdx.x * 128;
    int base = g_base[e];

    int tid = threadIdx.x, wid = tid >> 5, lane = tid & 31;
    int wm = wid & 3, wn = wid >> 2;
    uint32_t smb = smaddr(smem);

    const __half* A_g = PASS1 ? gx16 : gact16;
    const __half* B_g = PASS1 ? gw1  : gw2;

    // loader: plane p = tid>>7 (0=A,1=B), row r = tid&127, 32B per chunk
    int p = tid >> 7, r = tid & 127;
    const char* src;
    if (p == 0) {
        int mr = m0 + r; if (mr >= cnt) mr = cnt - 1;
        int ar = PASS1 ? g_perm[base + mr] : (base + mr);
        src = (const char*)(A_g + (size_t)ar * KDIM);
    } else {
        src = (const char*)(B_g + ((size_t)e * NDIM + n0 + r) * KDIM);
    }
    int s = (r >> 2) & 1;
    uint32_t d0 = (uint32_t)(p*PLB + r*32 + s*16);
    uint32_t d1 = (uint32_t)(p*PLB + r*32 + (s^1)*16);

    float acc[2][8][4];
#pragma unroll
    for (int a = 0; a < 2; a++)
#pragma unroll
        for (int b = 0; b < 8; b++)
#pragma unroll
            for (int c = 0; c < 4; c++) acc[a][b][c] = 0.f;

    // ldmatrix lane addressing (fragment mapping proven R3..R11)
    const int a_r = lane & 15, ac = lane >> 4;
    const int b_n = ((lane >> 4) & 1) * 8 + (lane & 7);
    const int bc  = (lane >> 3) & 1;

    const int NCH = KDIM / 16;   // 32 or 128 (even, >=4)

    // prologue: chunks 0,1 into stages 0,1
    {
        cp16(smb + 0*STGB + d0, src);        cp16(smb + 0*STGB + d1, src + 16);
        cp16(smb + 1*STGB + d0, src + 32);   cp16(smb + 1*STGB + d1, src + 48);
        CPC();
    }

    for (int ci = 0; ci < NCH; ci += 2) {
        cpw<0>();
        __syncthreads();
        if (ci + 2 < NCH) {
            uint32_t sgA = smb + ((ci + 2) & 3) * STGB;
            uint32_t sgB = smb + ((ci + 3) & 3) * STGB;
            uint32_t go  = (uint32_t)(ci + 2) * 32;
            cp16(sgA + d0, src + go);       cp16(sgA + d1, src + go + 16);
            cp16(sgB + d0, src + go + 32);  cp16(sgB + d1, src + go + 48);
            CPC();
        }

#pragma unroll
        for (int j = 0; j < 2; j++) {
            uint32_t sb = smb + ((ci + j) & 3) * STGB;
            uint32_t ah[2][4];
#pragma unroll
            for (int mt = 0; mt < 2; mt++) {
                int row = wm*32 + mt*16 + a_r;
                uint32_t co = (uint32_t)((ac ^ ((row >> 2) & 1)) * 16);
                ldmx4(ah[mt], sb + row*32 + co);
            }
#pragma unroll
            for (int p4 = 0; p4 < 4; p4++) {
                int row = wn*64 + p4*16 + b_n;
                uint32_t co = (uint32_t)((bc ^ ((row >> 2) & 1)) * 16);
                uint32_t bh[4];
                ldmx4(bh, sb + PLB + row*32 + co);
#pragma unroll
                for (int mt = 0; mt < 2; mt++) {
                    hmma(acc[mt][p4*2 + 0], ah[mt], &bh[0]);
                    hmma(acc[mt][p4*2 + 1], ah[mt], &bh[2]);
                }
            }
        }
    }

    // epilogue
    int rbase = wm*32 + (lane >> 2);
    int cbase = n0 + wn*64 + (lane & 3)*2;
#pragma unroll
    for (int mt = 0; mt < 2; mt++) {
#pragma unroll
        for (int sub = 0; sub < 2; sub++) {
            int m = m0 + rbase + mt*16 + sub*8;
            if (m >= cnt) continue;
            int slot = base + m;
            float wtv = PASS1 ? 1.f : g_wt[slot];
#pragma unroll
            for (int nt = 0; nt < 8; nt++) {
                int n = cbase + nt*8;
                float v0 = acc[mt][nt][sub*2+0] + __ldg(&bias[e*NDIM + n]);
                float v1 = acc[mt][nt][sub*2+1] + __ldg(&bias[e*NDIM + n + 1]);
                if (PASS1) {
                    v0 = v0 / (1.f + __expf(-v0));
                    v1 = v1 / (1.f + __expf(-v1));
                    uint32_t pk = (uint32_t)__half_as_ushort(__float2half_rn(v0))
                                | ((uint32_t)__half_as_ushort(__float2half_rn(v1)) << 16);
                    *(uint32_t*)(gact16 + (size_t)slot * NDIM + n) = pk;
                } else {
                    float2 o; o.x = v0 * wtv; o.y = v1 * wtv;
                    *(float2*)(gyy + (size_t)slot * NDIM + n) = o;
                }
            }
        }
    }
}

// ---------------- combine ----------------
__global__ void combine_kernel(float* __restrict__ out) {
    int idx = blockIdx.x * 256 + threadIdx.x;
    if (idx >= TOK * (HD/4)) return;
    int t  = idx / (HD/4);
    int h4 = idx % (HD/4);
    int s0 = g_slot_of[t*2+0];
    int s1 = g_slot_of[t*2+1];
    float4 a = *(const float4*)&gyy[(size_t)s0 * HD + h4*4];
    float4 b = *(const float4*)&gyy[(size_t)s1 * HD + h4*4];
    float4 o;
    o.x = a.x + b.x; o.y = a.y + b.y; o.z = a.z + b.z; o.w = a.w + b.w;
    *(float4*)&out[(size_t)t * HD + h4*4] = o;
}

// ---------------- launch ----------------
extern "C" void kernel_launch(void* const* d_in, const int* in_sizes, int n_in,
                              void* d_out, int out_size) {
    const float* x  = (const float*)d_in[0];
    const float* Wg = (const float*)d_in[1];
    const float* W1 = (const float*)d_in[2];  // [8][512][2048]
    const float* b1 = (const float*)d_in[3];
    const float* W2 = (const float*)d_in[4];  // [8][2048][512]
    const float* b2 = (const float*)d_in[5];
    float* out = (float*)d_out;

    init_kernel<<<1, 32>>>();
    w_transpose_kernel<HD, FD, true ><<<dim3(FD/32, HD/64, NE), dim3(32, 8)>>>(W1);
    w_transpose_kernel<FD, HD, false><<<dim3(HD/32, FD/64, NE), dim3(32, 8)>>>(W2);
    router_cvt_kernel<<<TOK/8, 256>>>(x, Wg);
    scan_kernel<<<1, 1>>>();
    scatter_kernel<<<TOK/256, 256>>>();

    // Pass A: gather(fp16 x) @ W1T -> silu -> gact16  (cnt_e <= 2048 -> <=16 m-tiles)
    moe_gemm_p2<HD, FD, true><<<dim3(FD/128, 16, NE), 256>>>(b1);
    // Pass B: gact16 @ W2T -> *wt -> gyy
    moe_gemm_p2<FD, HD, false><<<dim3(HD/128, 16, NE), 256>>>(b2);

    combine_kernel<<<(TOK*(HD/4) + 255)/256, 256>>>(out);
}